// round 1
// baseline (speedup 1.0000x reference)
#include <cuda_runtime.h>

#define NTOK 4096
#define CDIM 32
#define ROWS 32
#define SPLIT 8
#define NTHREADS 256
#define TI 32
#define JCHUNK (NTOK / SPLIT)
#define MAXB 2

// scratch for per-row softmax stats (no allocations allowed in kernel_launch)
__device__ float g_m[MAXB * NTOK];
__device__ float g_invz[MAXB * NTOK];

typedef unsigned long long u64;

__device__ __forceinline__ u64 ffma2(u64 a, u64 b, u64 c) {
    u64 d;
    asm("fma.rn.f32x2 %0, %1, %2, %3;" : "=l"(d) : "l"(a), "l"(b), "l"(c));
    return d;
}
__device__ __forceinline__ float2 unpack2(u64 v) {
    float2 r;
    asm("mov.b64 {%0, %1}, %2;" : "=f"(r.x), "=f"(r.y) : "l"(v));
    return r;
}
__device__ __forceinline__ u64 pack2(float lo, float hi) {
    u64 v;
    asm("mov.b64 %0, {%1, %2};" : "=l"(v) : "f"(lo), "f"(hi));
    return v;
}

// ---------------------------------------------------------------------------
// Pass 1: per-row online softmax stats. One thread per row i (32 rows/block),
// 8 warps each scan a disjoint 512-wide j-chunk; partial (m,Z) merged in smem.
// ---------------------------------------------------------------------------
__global__ void __launch_bounds__(NTHREADS, 2)
pass1_kernel(const float* __restrict__ x) {
    __shared__ u64 smx[SPLIT][TI][CDIM / 2];   // 32 KB, per-warp staging tiles
    __shared__ float red_m[SPLIT][ROWS];
    __shared__ float red_z[SPLIT][ROWS];

    const int bb   = blockIdx.y;
    const int lane = threadIdx.x & 31;
    const int sp   = threadIdx.x >> 5;
    const int i    = blockIdx.x * ROWS + lane;
    const float* xb = x + (size_t)bb * NTOK * CDIM;

    u64 rx[CDIM / 2];
    {
        const ulonglong2* p = reinterpret_cast<const ulonglong2*>(xb + (size_t)i * CDIM);
#pragma unroll
        for (int k = 0; k < CDIM / 4; k++) {
            ulonglong2 v = p[k];
            rx[2 * k] = v.x; rx[2 * k + 1] = v.y;
        }
    }

    float m = -1e30f, Z = 0.f;
    const int j0 = sp * JCHUNK;

    for (int t = 0; t < JCHUNK; t += TI) {
        // coalesced linear copy of the 32x32 fp32 tile into this warp's slab
        const ulonglong2* gp =
            reinterpret_cast<const ulonglong2*>(xb + (size_t)(j0 + t) * CDIM);
        ulonglong2* sg = reinterpret_cast<ulonglong2*>(&smx[sp][0][0]);
        __syncwarp();
#pragma unroll
        for (int k = 0; k < 8; k++) sg[k * 32 + lane] = gp[k * 32 + lane];
        __syncwarp();

#pragma unroll 2
        for (int jj = 0; jj < TI; jj++) {
            const ulonglong2* q = reinterpret_cast<const ulonglong2*>(&smx[sp][jj][0]);
            u64 sa = 0ull, sb = 0ull;
#pragma unroll
            for (int k = 0; k < CDIM / 4; k++) {
                ulonglong2 v = q[k];            // broadcast LDS.128
                sa = ffma2(v.x, rx[2 * k], sa);
                sb = ffma2(v.y, rx[2 * k + 1], sb);
            }
            float2 fa = unpack2(sa), fb = unpack2(sb);
            float s = (fa.x + fa.y) + (fb.x + fb.y);
            float mn = fmaxf(m, s);
            Z = Z * __expf(m - mn) + __expf(s - mn);
            m = mn;
        }
    }

    red_m[sp][lane] = m;
    red_z[sp][lane] = Z;
    __syncthreads();

    if (threadIdx.x < ROWS) {
        int r = threadIdx.x;
        float M = red_m[0][r];
#pragma unroll
        for (int g2 = 1; g2 < SPLIT; g2++) M = fmaxf(M, red_m[g2][r]);
        float Zt = 0.f;
#pragma unroll
        for (int g2 = 0; g2 < SPLIT; g2++)
            Zt += red_z[g2][r] * __expf(red_m[g2][r] - M);
        int gi = bb * NTOK + blockIdx.x * ROWS + r;
        g_m[gi]    = M;
        g_invz[gi] = 1.0f / Zt;
    }
}

// ---------------------------------------------------------------------------
// Pass 2: out[j,c] = sum_i exp(s_ij - m_i)/Z_i * x[i,c]; then *gamma + input.
// One thread per output row j, 8 warps split the i-range, partial acc vectors
// reduced through smem at the end.
// ---------------------------------------------------------------------------
__global__ void __launch_bounds__(NTHREADS, 2)
pass2_kernel(const float* __restrict__ x, const float* __restrict__ gamma,
             float* __restrict__ out) {
    __shared__ u64 smx[SPLIT][TI][CDIM / 2];   // staging, reused as reduction buf
    __shared__ float smm[SPLIT][TI];
    __shared__ float smz[SPLIT][TI];

    const int bb   = blockIdx.y;
    const int lane = threadIdx.x & 31;
    const int sp   = threadIdx.x >> 5;
    const int j    = blockIdx.x * ROWS + lane;
    const float* xb = x + (size_t)bb * NTOK * CDIM;

    u64 rx[CDIM / 2];
    {
        const ulonglong2* p = reinterpret_cast<const ulonglong2*>(xb + (size_t)j * CDIM);
#pragma unroll
        for (int k = 0; k < CDIM / 4; k++) {
            ulonglong2 v = p[k];
            rx[2 * k] = v.x; rx[2 * k + 1] = v.y;
        }
    }

    u64 acc[CDIM / 2];
#pragma unroll
    for (int k = 0; k < CDIM / 2; k++) acc[k] = 0ull;

    const int i0 = sp * JCHUNK;

    for (int t = 0; t < JCHUNK; t += TI) {
        const ulonglong2* gp =
            reinterpret_cast<const ulonglong2*>(xb + (size_t)(i0 + t) * CDIM);
        ulonglong2* sg = reinterpret_cast<ulonglong2*>(&smx[sp][0][0]);
        __syncwarp();
#pragma unroll
        for (int k = 0; k < 8; k++) sg[k * 32 + lane] = gp[k * 32 + lane];
        smm[sp][lane] = g_m[bb * NTOK + i0 + t + lane];
        smz[sp][lane] = g_invz[bb * NTOK + i0 + t + lane];
        __syncwarp();

        for (int ii = 0; ii < TI; ii++) {
            const ulonglong2* q = reinterpret_cast<const ulonglong2*>(&smx[sp][ii][0]);
            u64 va[CDIM / 2];
            u64 sa = 0ull, sb = 0ull;
#pragma unroll
            for (int k = 0; k < CDIM / 4; k++) {
                ulonglong2 v = q[k];            // broadcast LDS.128
                va[2 * k] = v.x; va[2 * k + 1] = v.y;
                sa = ffma2(v.x, rx[2 * k], sa);
                sb = ffma2(v.y, rx[2 * k + 1], sb);
            }
            float2 fa = unpack2(sa), fb = unpack2(sb);
            float s = (fa.x + fa.y) + (fb.x + fb.y);
            float w = __expf(s - smm[sp][ii]) * smz[sp][ii];
            u64 w2 = pack2(w, w);
#pragma unroll
            for (int k = 0; k < CDIM / 2; k++) acc[k] = ffma2(w2, va[k], acc[k]);
        }
    }

    // cross-warp reduction of the 32 per-row accumulators
    __syncthreads();
#pragma unroll
    for (int k = 0; k < CDIM / 2; k++) smx[sp][lane][k] = acc[k];
    __syncthreads();

    const float g = gamma[0];
    for (int u = threadIdx.x; u < ROWS * (CDIM / 2); u += NTHREADS) {
        int r = u >> 4;        // row within block
        int k = u & 15;        // f32x2 index within row
        float sx = 0.f, sy = 0.f;
#pragma unroll
        for (int g2 = 0; g2 < SPLIT; g2++) {
            float2 f = unpack2(smx[g2][r][k]);
            sx += f.x; sy += f.y;
        }
        int jj = blockIdx.x * ROWS + r;
        size_t base = ((size_t)bb * NTOK + jj) * CDIM + 2 * k;
        float2 inp = *reinterpret_cast<const float2*>(x + base);
        float2 o;
        o.x = sx * g + inp.x;
        o.y = sy * g + inp.y;
        *reinterpret_cast<float2*>(out + base) = o;
    }
}

extern "C" void kernel_launch(void* const* d_in, const int* in_sizes, int n_in,
                              void* d_out, int out_size) {
    const float* x     = (const float*)d_in[0];
    const float* gamma = (const float*)d_in[1];
    float* out = (float*)d_out;

    int b = in_sizes[0] / (NTOK * CDIM);
    if (b < 1) b = 1;
    if (b > MAXB) b = MAXB;

    dim3 grid(NTOK / ROWS, b);
    pass1_kernel<<<grid, NTHREADS>>>(x);
    pass2_kernel<<<grid, NTHREADS>>>(x, gamma, out);
}